// round 5
// baseline (speedup 1.0000x reference)
#include <cuda_runtime.h>
#include <cstdint>

#define NN 100000
#define EE 3200000
#define D_IN 512
#define D_HID 16
#define N_CLS 7

typedef unsigned long long ull;

// Scratch (device globals: allocation-free per harness rules)
__device__ __align__(16) float g_h1[NN * D_HID];     // x @ W1
__device__ __align__(16) float g_agg1[NN * D_HID];   // scatter-add of h1
__device__ __align__(16) float g_h2[NN * 8];         // relu(agg1+b1) @ W2, padded 7->8
__device__ __align__(16) float g_agg2[NN * 8];       // scatter-add of h2, padded
__device__ int g_is64;                               // edge-index dtype flag

__device__ __forceinline__ void red_add_v4(float* addr, float4 v) {
    asm volatile("{ .reg .u64 ga;\n\t"
                 "cvta.to.global.u64 ga, %0;\n\t"
                 "red.global.add.v4.f32 [ga], {%1,%2,%3,%4}; }"
                 :: "l"(addr), "f"(v.x), "f"(v.y), "f"(v.z), "f"(v.w)
                 : "memory");
}

// Packed f32x2 FMA: a += x * w elementwise on two packed floats.
__device__ __forceinline__ void fma2(ull& a, ull x, ull w) {
    asm("fma.rn.f32x2 %0, %1, %2, %0;" : "+l"(a) : "l"(x), "l"(w));
}
__device__ __forceinline__ float fold2(ull a) {
    float lo, hi;
    asm("mov.b64 {%0,%1}, %2;" : "=f"(lo), "=f"(hi) : "l"(a));
    return lo + hi;
}

// ---------------------------------------------------------------------------
// Init: zero accumulators (every launch: graph replay) + edge dtype detect.
// int64 node-ids (<2^31) have all-zero odd 32b words.
// ---------------------------------------------------------------------------
__global__ void k_init(const int* __restrict__ ei) {
    int i = blockIdx.x * blockDim.x + threadIdx.x;
    if (i == 0) {
        int s = 0;
        #pragma unroll
        for (int t = 1; t < 64; t += 2) s |= ei[t];
        g_is64 = (s == 0) ? 1 : 0;
    }
    float4 z = make_float4(0.f, 0.f, 0.f, 0.f);
    if (i < NN * 4) {                       // agg1: NN*16 floats = NN*4 float4
        reinterpret_cast<float4*>(g_agg1)[i] = z;
    }
    int j = i - NN * 4;
    if (j >= 0 && j < NN * 2) {             // agg2: NN*8 floats = NN*2 float4
        reinterpret_cast<float4*>(g_agg2)[j] = z;
    }
}

// ---------------------------------------------------------------------------
// GEMM1: g_h1 = x @ W1.  One warp per 4 nodes, split-K across 32 lanes,
// packed f32x2 FMAs. x streamed from global with __ldcs (no L2 pollution),
// software-pipelined one i-iteration ahead. W1^T staged in smem.
// ---------------------------------------------------------------------------
#define WPITCH_F 514          // floats per j-row
#define WPITCH_U 257          // ull per j-row

__device__ __forceinline__ void warp_reduce16_store(float v[16], int lane, float* dst) {
    // Halving-merge butterfly: 16 values x 32 lanes -> each lane-pair owns one j.
    #pragma unroll
    for (int t = 0; t < 8; t++) {
        bool hi = (lane & 16) != 0;
        float keep = hi ? v[t + 8] : v[t];
        float give = hi ? v[t] : v[t + 8];
        v[t] = keep + __shfl_xor_sync(0xffffffffu, give, 16);
    }
    #pragma unroll
    for (int t = 0; t < 4; t++) {
        bool hi = (lane & 8) != 0;
        float keep = hi ? v[t + 4] : v[t];
        float give = hi ? v[t] : v[t + 4];
        v[t] = keep + __shfl_xor_sync(0xffffffffu, give, 8);
    }
    #pragma unroll
    for (int t = 0; t < 2; t++) {
        bool hi = (lane & 4) != 0;
        float keep = hi ? v[t + 2] : v[t];
        float give = hi ? v[t] : v[t + 2];
        v[t] = keep + __shfl_xor_sync(0xffffffffu, give, 4);
    }
    {
        bool hi = (lane & 2) != 0;
        float keep = hi ? v[1] : v[0];
        float give = hi ? v[0] : v[1];
        v[0] = keep + __shfl_xor_sync(0xffffffffu, give, 2);
    }
    v[0] += __shfl_xor_sync(0xffffffffu, v[0], 1);
    // After the masks {16,8,4,2}, lane pair (2p, 2p+1) owns j = (lane>>1)&15.
    if ((lane & 1) == 0) dst[(lane >> 1) & 15] = v[0];
}

__global__ __launch_bounds__(128) void k_gemm1(const float* __restrict__ x,
                                               const float* __restrict__ W1) {
    __shared__ float wsf[16 * WPITCH_F];   // wsf[j*514 + k] = W1[k][j]
    int tid = threadIdx.x;
    #pragma unroll
    for (int t = 0; t < 64; t++) {
        int idx = tid + t * 128;           // 0..8191, coalesced W1 reads
        int k = idx >> 4;
        int j = idx & 15;
        wsf[j * WPITCH_F + k] = W1[idx];
    }
    __syncthreads();
    const ull* ws2 = reinterpret_cast<const ull*>(wsf);

    int warp = tid >> 5, lane = tid & 31;
    int node0 = blockIdx.x * 16 + warp * 4;        // NN = 6250*16 exactly
    const ull* xp = reinterpret_cast<const ull*>(x + (size_t)node0 * D_IN) + lane;

    ull a0[16], a1[16], a2[16], a3[16];
    #pragma unroll
    for (int j = 0; j < 16; j++) { a0[j] = a1[j] = a2[j] = a3[j] = 0ull; }

    // Software pipeline: prefetch next i-iteration's x while doing FMAs.
    ull x0 = __ldcs(xp +   0);
    ull x1 = __ldcs(xp + 256);
    ull x2 = __ldcs(xp + 512);
    ull x3 = __ldcs(xp + 768);
    #pragma unroll
    for (int i = 0; i < 8; i++) {
        ull nx0, nx1, nx2, nx3;
        if (i < 7) {
            nx0 = __ldcs(xp + (i + 1) * 32);
            nx1 = __ldcs(xp + (i + 1) * 32 + 256);
            nx2 = __ldcs(xp + (i + 1) * 32 + 512);
            nx3 = __ldcs(xp + (i + 1) * 32 + 768);
        }
        const ull* wk = ws2 + i * 32 + lane;
        #pragma unroll
        for (int j = 0; j < 16; j++) {
            ull w = wk[j * WPITCH_U];      // lanes consecutive 8B: conflict-free
            fma2(a0[j], x0, w);
            fma2(a1[j], x1, w);
            fma2(a2[j], x2, w);
            fma2(a3[j], x3, w);
        }
        if (i < 7) { x0 = nx0; x1 = nx1; x2 = nx2; x3 = nx3; }
    }

    float v[16];
    #pragma unroll
    for (int j = 0; j < 16; j++) v[j] = fold2(a0[j]);
    warp_reduce16_store(v, lane, g_h1 + (size_t)(node0 + 0) * 16);
    #pragma unroll
    for (int j = 0; j < 16; j++) v[j] = fold2(a1[j]);
    warp_reduce16_store(v, lane, g_h1 + (size_t)(node0 + 1) * 16);
    #pragma unroll
    for (int j = 0; j < 16; j++) v[j] = fold2(a2[j]);
    warp_reduce16_store(v, lane, g_h1 + (size_t)(node0 + 2) * 16);
    #pragma unroll
    for (int j = 0; j < 16; j++) v[j] = fold2(a3[j]);
    warp_reduce16_store(v, lane, g_h1 + (size_t)(node0 + 3) * 16);
}

// ---------------------------------------------------------------------------
// Scatter1: agg1[dst] += h1[src].  4 lanes per edge (one 16B chunk each) so
// gathers of a 64B row coalesce into the same 128B line. 8 edges per warp.
// ---------------------------------------------------------------------------
__global__ __launch_bounds__(256) void k_scatter1(const void* __restrict__ ei) {
    int warpGlobal = (blockIdx.x * 256 + threadIdx.x) >> 5;
    int lane = threadIdx.x & 31;
    int e_base = warpGlobal * 8;                  // EE = 50000*8*8 exactly
    int s = 0, d = 0;
    if (lane < 8) {
        int e = e_base + lane;
        if (g_is64) {
            const long long* p = (const long long*)ei;
            s = (int)p[e];
            d = (int)p[EE + e];
        } else {
            const int* p = (const int*)ei;
            s = p[e];
            d = p[EE + e];
        }
    }
    int eloc = lane >> 2;
    int src = __shfl_sync(0xffffffffu, s, eloc);
    int dst = __shfl_sync(0xffffffffu, d, eloc);
    if ((unsigned)src >= NN || (unsigned)dst >= NN) return;
    int chunk = lane & 3;
    float4 v = reinterpret_cast<const float4*>(g_h1)[src * 4 + chunk];
    red_add_v4(g_agg1 + (size_t)dst * 16 + chunk * 4, v);
}

// ---------------------------------------------------------------------------
// GEMM2: g_h2 = relu(agg1 + b1) @ W2  (row padded to 8 floats, last = 0)
// ---------------------------------------------------------------------------
__global__ __launch_bounds__(256) void k_gemm2(const float* __restrict__ b1,
                                               const float* __restrict__ W2) {
    __shared__ float w2s[16 * 7];
    __shared__ float b1s[16];
    if (threadIdx.x < 112) w2s[threadIdx.x] = W2[threadIdx.x];
    if (threadIdx.x < 16)  b1s[threadIdx.x] = b1[threadIdx.x];
    __syncthreads();

    int n = blockIdx.x * blockDim.x + threadIdx.x;
    if (n >= NN) return;

    const float4* ap = reinterpret_cast<const float4*>(g_agg1 + (size_t)n * 16);
    float h[16];
    float4 t0 = ap[0], t1 = ap[1], t2 = ap[2], t3 = ap[3];
    h[0] = t0.x; h[1] = t0.y; h[2]  = t0.z; h[3]  = t0.w;
    h[4] = t1.x; h[5] = t1.y; h[6]  = t1.z; h[7]  = t1.w;
    h[8] = t2.x; h[9] = t2.y; h[10] = t2.z; h[11] = t2.w;
    h[12] = t3.x; h[13] = t3.y; h[14] = t3.z; h[15] = t3.w;
    #pragma unroll
    for (int j = 0; j < 16; j++) h[j] = fmaxf(h[j] + b1s[j], 0.f);

    float o[8];
    #pragma unroll
    for (int c = 0; c < 7; c++) {
        float s = 0.f;
        #pragma unroll
        for (int j = 0; j < 16; j++) s = fmaf(h[j], w2s[j * 7 + c], s);
        o[c] = s;
    }
    o[7] = 0.f;

    float4* op = reinterpret_cast<float4*>(g_h2 + (size_t)n * 8);
    op[0] = make_float4(o[0], o[1], o[2], o[3]);
    op[1] = make_float4(o[4], o[5], o[6], o[7]);
}

// ---------------------------------------------------------------------------
// Scatter2: agg2[dst] += h2[src].  2 lanes per edge, 16 edges per warp.
// ---------------------------------------------------------------------------
__global__ __launch_bounds__(256) void k_scatter2(const void* __restrict__ ei) {
    int warpGlobal = (blockIdx.x * 256 + threadIdx.x) >> 5;
    int lane = threadIdx.x & 31;
    int e_base = warpGlobal * 16;                 // EE = 25000*8*16 exactly
    int s = 0, d = 0;
    if (lane < 16) {
        int e = e_base + lane;
        if (g_is64) {
            const long long* p = (const long long*)ei;
            s = (int)p[e];
            d = (int)p[EE + e];
        } else {
            const int* p = (const int*)ei;
            s = p[e];
            d = p[EE + e];
        }
    }
    int eloc = lane >> 1;
    int src = __shfl_sync(0xffffffffu, s, eloc);
    int dst = __shfl_sync(0xffffffffu, d, eloc);
    if ((unsigned)src >= NN || (unsigned)dst >= NN) return;
    int chunk = lane & 1;
    float4 v = reinterpret_cast<const float4*>(g_h2)[src * 2 + chunk];
    red_add_v4(g_agg2 + (size_t)dst * 8 + chunk * 4, v);
}

// ---------------------------------------------------------------------------
// Epilogue: out[n][c] = agg2[n][c] + b2[c]   (strips the padding)
// ---------------------------------------------------------------------------
__global__ void k_final(const float* __restrict__ b2, float* __restrict__ out) {
    int i = blockIdx.x * blockDim.x + threadIdx.x;
    if (i >= NN * N_CLS) return;
    int n = i / 7;
    int c = i - n * 7;
    out[i] = g_agg2[n * 8 + c] + b2[c];
}

// ---------------------------------------------------------------------------
extern "C" void kernel_launch(void* const* d_in, const int* in_sizes, int n_in,
                              void* d_out, int out_size) {
    // Map inputs by element count (all six are distinct) — immune to ordering.
    const float* x  = nullptr;
    const void*  ei = nullptr;
    const float* W1 = nullptr;
    const float* b1 = nullptr;
    const float* W2 = nullptr;
    const float* b2 = nullptr;
    for (int i = 0; i < n_in; i++) {
        switch (in_sizes[i]) {
            case NN * D_IN:        x  = (const float*)d_in[i]; break;  // 51,200,000
            case 2 * EE:           ei = d_in[i];                break;  // 6,400,000
            case D_IN * D_HID:     W1 = (const float*)d_in[i]; break;  // 8192
            case D_HID:            b1 = (const float*)d_in[i]; break;  // 16
            case D_HID * N_CLS:    W2 = (const float*)d_in[i]; break;  // 112
            case N_CLS:            b2 = (const float*)d_in[i]; break;  // 7
            default: break;
        }
    }
    float* out = (float*)d_out;

    k_init<<<(NN * 6 + 255) / 256, 256>>>((const int*)ei);
    k_gemm1<<<NN / 16, 128>>>(x, W1);
    k_scatter1<<<EE / 64, 256>>>(ei);
    k_gemm2<<<(NN + 255) / 256, 256>>>(b1, W2);
    k_scatter2<<<EE / 128, 256>>>(ei);
    k_final<<<(NN * N_CLS + 255) / 256, 256>>>(b2, out);
}

// round 6
// speedup vs baseline: 1.0433x; 1.0433x over previous
#include <cuda_runtime.h>
#include <cstdint>

#define NN 100000
#define EE 3200000
#define D_IN 512
#define D_HID 16
#define N_CLS 7

typedef unsigned long long ull;

// Scratch (device globals: allocation-free per harness rules)
__device__ __align__(16) float g_h1[NN * D_HID];     // x @ W1
__device__ __align__(16) float g_agg1[NN * D_HID];   // scatter-add of h1
__device__ __align__(16) float g_h2[NN * 8];         // relu(agg1+b1) @ W2, padded 7->8
__device__ __align__(16) float g_agg2[NN * 8];       // scatter-add of h2, padded
__device__ int g_is64;                               // edge-index dtype flag

__device__ __forceinline__ void red_add_v4(float* addr, float4 v) {
    asm volatile("{ .reg .u64 ga;\n\t"
                 "cvta.to.global.u64 ga, %0;\n\t"
                 "red.global.add.v4.f32 [ga], {%1,%2,%3,%4}; }"
                 :: "l"(addr), "f"(v.x), "f"(v.y), "f"(v.z), "f"(v.w)
                 : "memory");
}

// Packed f32x2 FMA: a += x * w elementwise on two packed floats.
__device__ __forceinline__ void fma2(ull& a, ull x, ull w) {
    asm("fma.rn.f32x2 %0, %1, %2, %0;" : "+l"(a) : "l"(x), "l"(w));
}
__device__ __forceinline__ float fold2(ull a) {
    float lo, hi;
    asm("mov.b64 {%0,%1}, %2;" : "=f"(lo), "=f"(hi) : "l"(a));
    return lo + hi;
}

// ---------------------------------------------------------------------------
// Init: zero accumulators (every launch: graph replay) + edge dtype detect.
// int64 node-ids (<2^31) have all-zero odd 32b words.
// ---------------------------------------------------------------------------
__global__ void k_init(const int* __restrict__ ei) {
    int i = blockIdx.x * blockDim.x + threadIdx.x;
    if (i == 0) {
        int s = 0;
        #pragma unroll
        for (int t = 1; t < 64; t += 2) s |= ei[t];
        g_is64 = (s == 0) ? 1 : 0;
    }
    float4 z = make_float4(0.f, 0.f, 0.f, 0.f);
    if (i < NN * 4) {                       // agg1: NN*16 floats = NN*4 float4
        reinterpret_cast<float4*>(g_agg1)[i] = z;
    }
    int j = i - NN * 4;
    if (j >= 0 && j < NN * 2) {             // agg2: NN*8 floats = NN*2 float4
        reinterpret_cast<float4*>(g_agg2)[j] = z;
    }
}

// ---------------------------------------------------------------------------
// GEMM1: g_h1 = x @ W1.  PERSISTENT blocks: W1^T staged in smem once, then
// grid-stride over node tiles (16 nodes/tile, 4 per warp). Split-K across 32
// lanes with packed f32x2 FMAs; x read coalesced from global (LDG.64/lane).
// ---------------------------------------------------------------------------
#define WPITCH_F 514          // floats per j-row
#define WPITCH_U 257          // ull per j-row
#define G1_BLOCKS 1250
#define G1_TILES  6250        // NN / 16

__device__ __forceinline__ void warp_reduce16_store(float v[16], int lane, float* dst) {
    // Halving-merge butterfly: 16 values x 32 lanes -> each lane-pair owns one j.
    #pragma unroll
    for (int t = 0; t < 8; t++) {
        bool hi = (lane & 16) != 0;
        float keep = hi ? v[t + 8] : v[t];
        float give = hi ? v[t] : v[t + 8];
        v[t] = keep + __shfl_xor_sync(0xffffffffu, give, 16);
    }
    #pragma unroll
    for (int t = 0; t < 4; t++) {
        bool hi = (lane & 8) != 0;
        float keep = hi ? v[t + 4] : v[t];
        float give = hi ? v[t] : v[t + 4];
        v[t] = keep + __shfl_xor_sync(0xffffffffu, give, 8);
    }
    #pragma unroll
    for (int t = 0; t < 2; t++) {
        bool hi = (lane & 4) != 0;
        float keep = hi ? v[t + 2] : v[t];
        float give = hi ? v[t] : v[t + 2];
        v[t] = keep + __shfl_xor_sync(0xffffffffu, give, 4);
    }
    {
        bool hi = (lane & 2) != 0;
        float keep = hi ? v[1] : v[0];
        float give = hi ? v[0] : v[1];
        v[0] = keep + __shfl_xor_sync(0xffffffffu, give, 2);
    }
    v[0] += __shfl_xor_sync(0xffffffffu, v[0], 1);
    // After the masks {16,8,4,2}, lane pair (2p, 2p+1) owns j = (lane>>1)&15.
    if ((lane & 1) == 0) dst[(lane >> 1) & 15] = v[0];
}

__global__ __launch_bounds__(128) void k_gemm1(const float* __restrict__ x,
                                               const float* __restrict__ W1) {
    __shared__ float wsf[16 * WPITCH_F];   // wsf[j*514 + k] = W1[k][j]
    int tid = threadIdx.x;
    #pragma unroll
    for (int t = 0; t < 64; t++) {
        int idx = tid + t * 128;           // 0..8191, coalesced W1 reads
        int k = idx >> 4;
        int j = idx & 15;
        wsf[j * WPITCH_F + k] = W1[idx];
    }
    __syncthreads();
    const ull* ws2 = reinterpret_cast<const ull*>(wsf);

    int warp = tid >> 5, lane = tid & 31;

    for (int tile = blockIdx.x; tile < G1_TILES; tile += G1_BLOCKS) {
        int node0 = tile * 16 + warp * 4;
        const ull* xp = reinterpret_cast<const ull*>(x + (size_t)node0 * D_IN) + lane;

        ull a0[16], a1[16], a2[16], a3[16];
        #pragma unroll
        for (int j = 0; j < 16; j++) { a0[j] = a1[j] = a2[j] = a3[j] = 0ull; }

        #pragma unroll
        for (int i = 0; i < 8; i++) {
            ull x0 = xp[i * 32];
            ull x1 = xp[i * 32 + 256];
            ull x2 = xp[i * 32 + 512];
            ull x3 = xp[i * 32 + 768];
            const ull* wk = ws2 + i * 32 + lane;
            #pragma unroll
            for (int j = 0; j < 16; j++) {
                ull w = wk[j * WPITCH_U];  // lanes consecutive 8B: conflict-free
                fma2(a0[j], x0, w);
                fma2(a1[j], x1, w);
                fma2(a2[j], x2, w);
                fma2(a3[j], x3, w);
            }
        }

        float v[16];
        #pragma unroll
        for (int j = 0; j < 16; j++) v[j] = fold2(a0[j]);
        warp_reduce16_store(v, lane, g_h1 + (size_t)(node0 + 0) * 16);
        #pragma unroll
        for (int j = 0; j < 16; j++) v[j] = fold2(a1[j]);
        warp_reduce16_store(v, lane, g_h1 + (size_t)(node0 + 1) * 16);
        #pragma unroll
        for (int j = 0; j < 16; j++) v[j] = fold2(a2[j]);
        warp_reduce16_store(v, lane, g_h1 + (size_t)(node0 + 2) * 16);
        #pragma unroll
        for (int j = 0; j < 16; j++) v[j] = fold2(a3[j]);
        warp_reduce16_store(v, lane, g_h1 + (size_t)(node0 + 3) * 16);
    }
}

// ---------------------------------------------------------------------------
// Scatter1: agg1[dst] += h1[src].  4 lanes per edge (one 16B chunk each) so
// gathers of a 64B row coalesce into the same 128B line. 8 edges per warp.
// ---------------------------------------------------------------------------
__global__ __launch_bounds__(256) void k_scatter1(const void* __restrict__ ei) {
    int warpGlobal = (blockIdx.x * 256 + threadIdx.x) >> 5;
    int lane = threadIdx.x & 31;
    int e_base = warpGlobal * 8;                  // EE = 50000*8*8 exactly
    int s = 0, d = 0;
    if (lane < 8) {
        int e = e_base + lane;
        if (g_is64) {
            const long long* p = (const long long*)ei;
            s = (int)p[e];
            d = (int)p[EE + e];
        } else {
            const int* p = (const int*)ei;
            s = p[e];
            d = p[EE + e];
        }
    }
    int eloc = lane >> 2;
    int src = __shfl_sync(0xffffffffu, s, eloc);
    int dst = __shfl_sync(0xffffffffu, d, eloc);
    if ((unsigned)src >= NN || (unsigned)dst >= NN) return;
    int chunk = lane & 3;
    float4 v = reinterpret_cast<const float4*>(g_h1)[src * 4 + chunk];
    red_add_v4(g_agg1 + (size_t)dst * 16 + chunk * 4, v);
}

// ---------------------------------------------------------------------------
// GEMM2: g_h2 = relu(agg1 + b1) @ W2  (row padded to 8 floats, last = 0)
// ---------------------------------------------------------------------------
__global__ __launch_bounds__(256) void k_gemm2(const float* __restrict__ b1,
                                               const float* __restrict__ W2) {
    __shared__ float w2s[16 * 7];
    __shared__ float b1s[16];
    if (threadIdx.x < 112) w2s[threadIdx.x] = W2[threadIdx.x];
    if (threadIdx.x < 16)  b1s[threadIdx.x] = b1[threadIdx.x];
    __syncthreads();

    int n = blockIdx.x * blockDim.x + threadIdx.x;
    if (n >= NN) return;

    const float4* ap = reinterpret_cast<const float4*>(g_agg1 + (size_t)n * 16);
    float h[16];
    float4 t0 = ap[0], t1 = ap[1], t2 = ap[2], t3 = ap[3];
    h[0] = t0.x; h[1] = t0.y; h[2]  = t0.z; h[3]  = t0.w;
    h[4] = t1.x; h[5] = t1.y; h[6]  = t1.z; h[7]  = t1.w;
    h[8] = t2.x; h[9] = t2.y; h[10] = t2.z; h[11] = t2.w;
    h[12] = t3.x; h[13] = t3.y; h[14] = t3.z; h[15] = t3.w;
    #pragma unroll
    for (int j = 0; j < 16; j++) h[j] = fmaxf(h[j] + b1s[j], 0.f);

    float o[8];
    #pragma unroll
    for (int c = 0; c < 7; c++) {
        float s = 0.f;
        #pragma unroll
        for (int j = 0; j < 16; j++) s = fmaf(h[j], w2s[j * 7 + c], s);
        o[c] = s;
    }
    o[7] = 0.f;

    float4* op = reinterpret_cast<float4*>(g_h2 + (size_t)n * 8);
    op[0] = make_float4(o[0], o[1], o[2], o[3]);
    op[1] = make_float4(o[4], o[5], o[6], o[7]);
}

// ---------------------------------------------------------------------------
// Scatter2: agg2[dst] += h2[src].  2 lanes per edge, 16 edges per warp.
// ---------------------------------------------------------------------------
__global__ __launch_bounds__(256) void k_scatter2(const void* __restrict__ ei) {
    int warpGlobal = (blockIdx.x * 256 + threadIdx.x) >> 5;
    int lane = threadIdx.x & 31;
    int e_base = warpGlobal * 16;                 // EE = 25000*8*16 exactly
    int s = 0, d = 0;
    if (lane < 16) {
        int e = e_base + lane;
        if (g_is64) {
            const long long* p = (const long long*)ei;
            s = (int)p[e];
            d = (int)p[EE + e];
        } else {
            const int* p = (const int*)ei;
            s = p[e];
            d = p[EE + e];
        }
    }
    int eloc = lane >> 1;
    int src = __shfl_sync(0xffffffffu, s, eloc);
    int dst = __shfl_sync(0xffffffffu, d, eloc);
    if ((unsigned)src >= NN || (unsigned)dst >= NN) return;
    int chunk = lane & 1;
    float4 v = reinterpret_cast<const float4*>(g_h2)[src * 2 + chunk];
    red_add_v4(g_agg2 + (size_t)dst * 8 + chunk * 4, v);
}

// ---------------------------------------------------------------------------
// Epilogue: out[n][c] = agg2[n][c] + b2[c]   (strips the padding)
// ---------------------------------------------------------------------------
__global__ void k_final(const float* __restrict__ b2, float* __restrict__ out) {
    int i = blockIdx.x * blockDim.x + threadIdx.x;
    if (i >= NN * N_CLS) return;
    int n = i / 7;
    int c = i - n * 7;
    out[i] = g_agg2[n * 8 + c] + b2[c];
}

// ---------------------------------------------------------------------------
extern "C" void kernel_launch(void* const* d_in, const int* in_sizes, int n_in,
                              void* d_out, int out_size) {
    // Map inputs by element count (all six are distinct) — immune to ordering.
    const float* x  = nullptr;
    const void*  ei = nullptr;
    const float* W1 = nullptr;
    const float* b1 = nullptr;
    const float* W2 = nullptr;
    const float* b2 = nullptr;
    for (int i = 0; i < n_in; i++) {
        switch (in_sizes[i]) {
            case NN * D_IN:        x  = (const float*)d_in[i]; break;  // 51,200,000
            case 2 * EE:           ei = d_in[i];                break;  // 6,400,000
            case D_IN * D_HID:     W1 = (const float*)d_in[i]; break;  // 8192
            case D_HID:            b1 = (const float*)d_in[i]; break;  // 16
            case D_HID * N_CLS:    W2 = (const float*)d_in[i]; break;  // 112
            case N_CLS:            b2 = (const float*)d_in[i]; break;  // 7
            default: break;
        }
    }
    float* out = (float*)d_out;

    k_init<<<(NN * 6 + 255) / 256, 256>>>((const int*)ei);
    k_gemm1<<<G1_BLOCKS, 128>>>(x, W1);
    k_scatter1<<<EE / 64, 256>>>(ei);
    k_gemm2<<<(NN + 255) / 256, 256>>>(b1, W2);
    k_scatter2<<<EE / 128, 256>>>(ei);
    k_final<<<(NN * N_CLS + 255) / 256, 256>>>(b2, out);
}

// round 8
// speedup vs baseline: 1.2630x; 1.2105x over previous
#include <cuda_runtime.h>
#include <cstdint>

#define NN 100000
#define EE 3200000
#define D_IN 512
#define D_HID 16
#define N_CLS 7

typedef unsigned long long ull;

// Scratch (device globals: allocation-free per harness rules)
__device__ __align__(16) float g_h1[NN * D_HID];     // x @ W1
__device__ __align__(16) float g_agg1[NN * D_HID];   // scatter-add of h1
__device__ __align__(16) float g_h2[NN * 8];         // relu(agg1+b1) @ W2, padded 7->8
__device__ __align__(16) float g_agg2[NN * 8];       // scatter-add of h2, padded
__device__ int g_is64;                               // edge-index dtype flag

__device__ __forceinline__ void red_add_v4(float* addr, float4 v) {
    asm volatile("{ .reg .u64 ga;\n\t"
                 "cvta.to.global.u64 ga, %0;\n\t"
                 "red.global.add.v4.f32 [ga], {%1,%2,%3,%4}; }"
                 :: "l"(addr), "f"(v.x), "f"(v.y), "f"(v.z), "f"(v.w)
                 : "memory");
}

// Packed f32x2 FMA: a += x * w elementwise on two packed floats.
__device__ __forceinline__ void fma2(ull& a, ull x, ull w) {
    asm("fma.rn.f32x2 %0, %1, %2, %0;" : "+l"(a) : "l"(x), "l"(w));
}

// ---------------------------------------------------------------------------
// Init: zero accumulators (every launch: graph replay) + edge dtype detect.
// int64 node-ids (<2^31) have all-zero odd 32b words.
// ---------------------------------------------------------------------------
__global__ void k_init(const int* __restrict__ ei) {
    int i = blockIdx.x * blockDim.x + threadIdx.x;
    if (i == 0) {
        int s = 0;
        #pragma unroll
        for (int t = 1; t < 64; t += 2) s |= ei[t];
        g_is64 = (s == 0) ? 1 : 0;
    }
    float4 z = make_float4(0.f, 0.f, 0.f, 0.f);
    if (i < NN * 4) {                       // agg1: NN*16 floats = NN*4 float4
        reinterpret_cast<float4*>(g_agg1)[i] = z;
    }
    int j = i - NN * 4;
    if (j >= 0 && j < NN * 2) {             // agg2: NN*8 floats = NN*2 float4
        reinterpret_cast<float4*>(g_agg2)[j] = z;
    }
}

// ---------------------------------------------------------------------------
// GEMM1: g_h1 = x @ W1.  Tiled: block = 128 nodes, 256 threads.
// Thread (m = tid>>1, jh = tid&1) owns node m and output half jh (8 j's)
// -> only 4 packed ull accumulators (8 regs) => high occupancy.
// K in 16 chunks of 32: x chunk staged TRANSPOSED in smem (xs[kk][m],
// pitch 129, conflict-free), W1 chunk (32x16) restaged per chunk.
// ---------------------------------------------------------------------------
#define G1_TM 128            // nodes per block
#define G1_KC 32             // K chunk
#define G1_NCHUNK (D_IN / G1_KC)
#define G1_XPITCH 129
#define G1_BLOCKS ((NN + G1_TM - 1) / G1_TM)   // 782

__global__ __launch_bounds__(256) void k_gemm1(const float* __restrict__ x,
                                               const float* __restrict__ W1) {
    __shared__ float xs[G1_KC][G1_XPITCH];   // transposed x chunk
    __shared__ float wsc[G1_KC][16];         // W1 chunk

    int tid = threadIdx.x;
    int m   = tid >> 1;          // node within block, 0..127
    int jh  = tid & 1;           // output half: j = 8*jh .. 8*jh+7
    int nbase = blockIdx.x * G1_TM;
    int gn = nbase + m;

    ull acc0 = 0, acc1 = 0, acc2 = 0, acc3 = 0;

    for (int kc = 0; kc < G1_NCHUNK; kc++) {
        __syncthreads();   // previous chunk's compute done before overwrite
        // Stage x chunk transposed: 128 nodes x 32 kk. Vectorized loads:
        // 1024 float4 / 256 threads = 4 each. Lanes: kk4 = (idx&7)*4, node = idx>>3.
        #pragma unroll
        for (int r = 0; r < 4; r++) {
            int idx = r * 256 + tid;          // 0..1023
            int kk4 = (idx & 7) * 4;
            int mm  = idx >> 3;               // 0..127
            int gm  = nbase + mm;
            float4 v = make_float4(0.f, 0.f, 0.f, 0.f);
            if (gm < NN)
                v = *reinterpret_cast<const float4*>(x + (size_t)gm * D_IN + kc * G1_KC + kk4);
            xs[kk4 + 0][mm] = v.x;            // banks (4h+g) all distinct: conflict-free
            xs[kk4 + 1][mm] = v.y;
            xs[kk4 + 2][mm] = v.z;
            xs[kk4 + 3][mm] = v.w;
        }
        // Stage W1 chunk: 512 floats / 256 threads = 2 each, coalesced.
        #pragma unroll
        for (int r = 0; r < 2; r++) {
            int idx = r * 256 + tid;          // 0..511
            (&wsc[0][0])[idx] = W1[kc * (G1_KC * 16) + idx];
        }
        __syncthreads();

        // Compute: 32 kk steps, 8 MAC-pairs each.
        #pragma unroll
        for (int kk = 0; kk < G1_KC; kk++) {
            float xv = xs[kk][m];                             // 2-way broadcast
            ull xv2;
            asm("mov.b64 %0, {%1,%1};" : "=l"(xv2) : "f"(xv));
            const ull* wp = reinterpret_cast<const ull*>(&wsc[kk][jh * 8]);
            fma2(acc0, xv2, wp[0]);
            fma2(acc1, xv2, wp[1]);
            fma2(acc2, xv2, wp[2]);
            fma2(acc3, xv2, wp[3]);
        }
    }

    if (gn < NN) {
        ulonglong2* op = reinterpret_cast<ulonglong2*>(g_h1 + (size_t)gn * 16 + jh * 8);
        ulonglong2 lo, hi;
        lo.x = acc0; lo.y = acc1;
        hi.x = acc2; hi.y = acc3;
        op[0] = lo;    // 16B store
        op[1] = hi;    // 16B store
    }
}

// ---------------------------------------------------------------------------
// Scatter1: agg1[dst] += h1[src].  4 lanes per edge (one 16B chunk each) so
// gathers of a 64B row coalesce into the same 128B line. 8 edges per warp.
// ---------------------------------------------------------------------------
__global__ __launch_bounds__(256) void k_scatter1(const void* __restrict__ ei) {
    int warpGlobal = (blockIdx.x * 256 + threadIdx.x) >> 5;
    int lane = threadIdx.x & 31;
    int e_base = warpGlobal * 8;                  // EE = 50000*8*8 exactly
    int s = 0, d = 0;
    if (lane < 8) {
        int e = e_base + lane;
        if (g_is64) {
            const long long* p = (const long long*)ei;
            s = (int)p[e];
            d = (int)p[EE + e];
        } else {
            const int* p = (const int*)ei;
            s = p[e];
            d = p[EE + e];
        }
    }
    int eloc = lane >> 2;
    int src = __shfl_sync(0xffffffffu, s, eloc);
    int dst = __shfl_sync(0xffffffffu, d, eloc);
    if ((unsigned)src >= NN || (unsigned)dst >= NN) return;
    int chunk = lane & 3;
    float4 v = reinterpret_cast<const float4*>(g_h1)[src * 4 + chunk];
    red_add_v4(g_agg1 + (size_t)dst * 16 + chunk * 4, v);
}

// ---------------------------------------------------------------------------
// GEMM2: g_h2 = relu(agg1 + b1) @ W2  (row padded to 8 floats, last = 0)
// ---------------------------------------------------------------------------
__global__ __launch_bounds__(256) void k_gemm2(const float* __restrict__ b1,
                                               const float* __restrict__ W2) {
    __shared__ float w2s[16 * 7];
    __shared__ float b1s[16];
    if (threadIdx.x < 112) w2s[threadIdx.x] = W2[threadIdx.x];
    if (threadIdx.x < 16)  b1s[threadIdx.x] = b1[threadIdx.x];
    __syncthreads();

    int n = blockIdx.x * blockDim.x + threadIdx.x;
    if (n >= NN) return;

    const float4* ap = reinterpret_cast<const float4*>(g_agg1 + (size_t)n * 16);
    float h[16];
    float4 t0 = ap[0], t1 = ap[1], t2 = ap[2], t3 = ap[3];
    h[0] = t0.x; h[1] = t0.y; h[2]  = t0.z; h[3]  = t0.w;
    h[4] = t1.x; h[5] = t1.y; h[6]  = t1.z; h[7]  = t1.w;
    h[8] = t2.x; h[9] = t2.y; h[10] = t2.z; h[11] = t2.w;
    h[12] = t3.x; h[13] = t3.y; h[14] = t3.z; h[15] = t3.w;
    #pragma unroll
    for (int j = 0; j < 16; j++) h[j] = fmaxf(h[j] + b1s[j], 0.f);

    float o[8];
    #pragma unroll
    for (int c = 0; c < 7; c++) {
        float s = 0.f;
        #pragma unroll
        for (int j = 0; j < 16; j++) s = fmaf(h[j], w2s[j * 7 + c], s);
        o[c] = s;
    }
    o[7] = 0.f;

    float4* op = reinterpret_cast<float4*>(g_h2 + (size_t)n * 8);
    op[0] = make_float4(o[0], o[1], o[2], o[3]);
    op[1] = make_float4(o[4], o[5], o[6], o[7]);
}

// ---------------------------------------------------------------------------
// Scatter2: agg2[dst] += h2[src].  2 lanes per edge, 16 edges per warp.
// ---------------------------------------------------------------------------
__global__ __launch_bounds__(256) void k_scatter2(const void* __restrict__ ei) {
    int warpGlobal = (blockIdx.x * 256 + threadIdx.x) >> 5;
    int lane = threadIdx.x & 31;
    int e_base = warpGlobal * 16;                 // EE = 25000*8*16 exactly
    int s = 0, d = 0;
    if (lane < 16) {
        int e = e_base + lane;
        if (g_is64) {
            const long long* p = (const long long*)ei;
            s = (int)p[e];
            d = (int)p[EE + e];
        } else {
            const int* p = (const int*)ei;
            s = p[e];
            d = p[EE + e];
        }
    }
    int eloc = lane >> 1;
    int src = __shfl_sync(0xffffffffu, s, eloc);
    int dst = __shfl_sync(0xffffffffu, d, eloc);
    if ((unsigned)src >= NN || (unsigned)dst >= NN) return;
    int chunk = lane & 1;
    float4 v = reinterpret_cast<const float4*>(g_h2)[src * 2 + chunk];
    red_add_v4(g_agg2 + (size_t)dst * 8 + chunk * 4, v);
}

// ---------------------------------------------------------------------------
// Epilogue: out[n][c] = agg2[n][c] + b2[c]   (strips the padding)
// ---------------------------------------------------------------------------
__global__ void k_final(const float* __restrict__ b2, float* __restrict__ out) {
    int i = blockIdx.x * blockDim.x + threadIdx.x;
    if (i >= NN * N_CLS) return;
    int n = i / 7;
    int c = i - n * 7;
    out[i] = g_agg2[n * 8 + c] + b2[c];
}

// ---------------------------------------------------------------------------
extern "C" void kernel_launch(void* const* d_in, const int* in_sizes, int n_in,
                              void* d_out, int out_size) {
    // Map inputs by element count (all six are distinct) — immune to ordering.
    const float* x  = nullptr;
    const void*  ei = nullptr;
    const float* W1 = nullptr;
    const float* b1 = nullptr;
    const float* W2 = nullptr;
    const float* b2 = nullptr;
    for (int i = 0; i < n_in; i++) {
        switch (in_sizes[i]) {
            case NN * D_IN:        x  = (const float*)d_in[i]; break;  // 51,200,000
            case 2 * EE:           ei = d_in[i];                break;  // 6,400,000
            case D_IN * D_HID:     W1 = (const float*)d_in[i]; break;  // 8192
            case D_HID:            b1 = (const float*)d_in[i]; break;  // 16
            case D_HID * N_CLS:    W2 = (const float*)d_in[i]; break;  // 112
            case N_CLS:            b2 = (const float*)d_in[i]; break;  // 7
            default: break;
        }
    }
    float* out = (float*)d_out;

    k_init<<<(NN * 6 + 255) / 256, 256>>>((const int*)ei);
    k_gemm1<<<G1_BLOCKS, 256>>>(x, W1);
    k_scatter1<<<EE / 64, 256>>>(ei);
    k_gemm2<<<(NN + 255) / 256, 256>>>(b1, W2);
    k_scatter2<<<EE / 128, 256>>>(ei);
    k_final<<<(NN * N_CLS + 255) / 256, 256>>>(b2, out);
}

// round 9
// speedup vs baseline: 1.4020x; 1.1101x over previous
#include <cuda_runtime.h>
#include <cstdint>

#define NN 100000
#define EE 3200000
#define D_IN 512
#define D_HID 16
#define N_CLS 7

typedef unsigned long long ull;

// Scratch (device globals: allocation-free per harness rules)
__device__ __align__(16) float g_h1[NN * D_HID];     // x @ W1
__device__ __align__(16) float g_agg1[NN * D_HID];   // scatter-add of h1
__device__ __align__(16) float g_h2[NN * 8];         // relu(agg1+b1) @ W2, padded 7->8
__device__ __align__(16) float g_agg2[NN * 8];       // scatter-add of h2, padded
__device__ int g_is64;                               // edge-index dtype flag

__device__ __forceinline__ void red_add_v4(float* addr, float4 v) {
    asm volatile("{ .reg .u64 ga;\n\t"
                 "cvta.to.global.u64 ga, %0;\n\t"
                 "red.global.add.v4.f32 [ga], {%1,%2,%3,%4}; }"
                 :: "l"(addr), "f"(v.x), "f"(v.y), "f"(v.z), "f"(v.w)
                 : "memory");
}

// Packed f32x2 FMA: a += x * w elementwise on two packed floats.
__device__ __forceinline__ void fma2(ull& a, ull x, ull w) {
    asm("fma.rn.f32x2 %0, %1, %2, %0;" : "+l"(a) : "l"(x), "l"(w));
}
__device__ __forceinline__ float fold2(ull a) {
    float lo, hi;
    asm("mov.b64 {%0,%1}, %2;" : "=f"(lo), "=f"(hi) : "l"(a));
    return lo + hi;
}

// ---------------------------------------------------------------------------
// Init: zero accumulators (every launch: graph replay) + edge dtype detect.
// int64 node-ids (<2^31) have all-zero odd 32b words.
// ---------------------------------------------------------------------------
__global__ void k_init(const int* __restrict__ ei) {
    int i = blockIdx.x * blockDim.x + threadIdx.x;
    if (i == 0) {
        int s = 0;
        #pragma unroll
        for (int t = 1; t < 64; t += 2) s |= ei[t];
        g_is64 = (s == 0) ? 1 : 0;
    }
    float4 z = make_float4(0.f, 0.f, 0.f, 0.f);
    if (i < NN * 4) {                       // agg1: NN*16 floats = NN*4 float4
        reinterpret_cast<float4*>(g_agg1)[i] = z;
    }
    int j = i - NN * 4;
    if (j >= 0 && j < NN * 2) {             // agg2: NN*8 floats = NN*2 float4
        reinterpret_cast<float4*>(g_agg2)[j] = z;
    }
}

// ---------------------------------------------------------------------------
// GEMM1: g_h1 = x @ W1.  One warp per 2 nodes (64 accumulator regs ->
// ~24 warps/SM), split-K across 32 lanes, packed f32x2 FMAs.
// 256 threads = 8 warps per block -> 16 nodes/block, same W1 staging as the
// proven round-3 shape. x read coalesced from global (LDG.64/lane);
// W1^T staged in smem, read as 8B packed pairs conflict-free.
// ---------------------------------------------------------------------------
#define WPITCH_F 514          // floats per j-row
#define WPITCH_U 257          // ull per j-row

__device__ __forceinline__ void warp_reduce16_store(float v[16], int lane, float* dst) {
    // Halving-merge butterfly: 16 values x 32 lanes -> each lane-pair owns one j.
    #pragma unroll
    for (int t = 0; t < 8; t++) {
        bool hi = (lane & 16) != 0;
        float keep = hi ? v[t + 8] : v[t];
        float give = hi ? v[t] : v[t + 8];
        v[t] = keep + __shfl_xor_sync(0xffffffffu, give, 16);
    }
    #pragma unroll
    for (int t = 0; t < 4; t++) {
        bool hi = (lane & 8) != 0;
        float keep = hi ? v[t + 4] : v[t];
        float give = hi ? v[t] : v[t + 4];
        v[t] = keep + __shfl_xor_sync(0xffffffffu, give, 8);
    }
    #pragma unroll
    for (int t = 0; t < 2; t++) {
        bool hi = (lane & 4) != 0;
        float keep = hi ? v[t + 2] : v[t];
        float give = hi ? v[t] : v[t + 2];
        v[t] = keep + __shfl_xor_sync(0xffffffffu, give, 4);
    }
    {
        bool hi = (lane & 2) != 0;
        float keep = hi ? v[1] : v[0];
        float give = hi ? v[0] : v[1];
        v[0] = keep + __shfl_xor_sync(0xffffffffu, give, 2);
    }
    v[0] += __shfl_xor_sync(0xffffffffu, v[0], 1);
    // After the masks {16,8,4,2}, lane pair (2p, 2p+1) owns j = (lane>>1)&15.
    if ((lane & 1) == 0) dst[(lane >> 1) & 15] = v[0];
}

__global__ __launch_bounds__(256) void k_gemm1(const float* __restrict__ x,
                                               const float* __restrict__ W1) {
    __shared__ float wsf[16 * WPITCH_F];   // wsf[j*514 + k] = W1[k][j]
    int tid = threadIdx.x;
    #pragma unroll
    for (int t = 0; t < 32; t++) {
        int idx = tid + t * 256;           // 0..8191, coalesced W1 reads
        int k = idx >> 4;
        int j = idx & 15;
        wsf[j * WPITCH_F + k] = W1[idx];
    }
    __syncthreads();
    const ull* ws2 = reinterpret_cast<const ull*>(wsf);

    int warp = tid >> 5, lane = tid & 31;
    int node0 = blockIdx.x * 16 + warp * 2;        // NN = 6250*16 exactly
    const ull* xp = reinterpret_cast<const ull*>(x + (size_t)node0 * D_IN) + lane;

    ull a0[16], a1[16];
    #pragma unroll
    for (int j = 0; j < 16; j++) { a0[j] = a1[j] = 0ull; }

    #pragma unroll
    for (int i = 0; i < 8; i++) {
        ull x0 = xp[i * 32];
        ull x1 = xp[i * 32 + 256];
        const ull* wk = ws2 + i * 32 + lane;
        #pragma unroll
        for (int j = 0; j < 16; j++) {
            ull w = wk[j * WPITCH_U];      // lanes consecutive 8B: conflict-free
            fma2(a0[j], x0, w);
            fma2(a1[j], x1, w);
        }
    }

    float v[16];
    #pragma unroll
    for (int j = 0; j < 16; j++) v[j] = fold2(a0[j]);
    warp_reduce16_store(v, lane, g_h1 + (size_t)(node0 + 0) * 16);
    #pragma unroll
    for (int j = 0; j < 16; j++) v[j] = fold2(a1[j]);
    warp_reduce16_store(v, lane, g_h1 + (size_t)(node0 + 1) * 16);
}

// ---------------------------------------------------------------------------
// Scatter1: agg1[dst] += h1[src].  4 lanes per edge (one 16B chunk each) so
// gathers of a 64B row coalesce into the same 128B line. 8 edges per warp.
// ---------------------------------------------------------------------------
__global__ __launch_bounds__(256) void k_scatter1(const void* __restrict__ ei) {
    int warpGlobal = (blockIdx.x * 256 + threadIdx.x) >> 5;
    int lane = threadIdx.x & 31;
    int e_base = warpGlobal * 8;                  // EE = 50000*8*8 exactly
    int s = 0, d = 0;
    if (lane < 8) {
        int e = e_base + lane;
        if (g_is64) {
            const long long* p = (const long long*)ei;
            s = (int)p[e];
            d = (int)p[EE + e];
        } else {
            const int* p = (const int*)ei;
            s = p[e];
            d = p[EE + e];
        }
    }
    int eloc = lane >> 2;
    int src = __shfl_sync(0xffffffffu, s, eloc);
    int dst = __shfl_sync(0xffffffffu, d, eloc);
    if ((unsigned)src >= NN || (unsigned)dst >= NN) return;
    int chunk = lane & 3;
    float4 v = reinterpret_cast<const float4*>(g_h1)[src * 4 + chunk];
    red_add_v4(g_agg1 + (size_t)dst * 16 + chunk * 4, v);
}

// ---------------------------------------------------------------------------
// GEMM2: g_h2 = relu(agg1 + b1) @ W2  (row padded to 8 floats, last = 0)
// ---------------------------------------------------------------------------
__global__ __launch_bounds__(256) void k_gemm2(const float* __restrict__ b1,
                                               const float* __restrict__ W2) {
    __shared__ float w2s[16 * 7];
    __shared__ float b1s[16];
    if (threadIdx.x < 112) w2s[threadIdx.x] = W2[threadIdx.x];
    if (threadIdx.x < 16)  b1s[threadIdx.x] = b1[threadIdx.x];
    __syncthreads();

    int n = blockIdx.x * blockDim.x + threadIdx.x;
    if (n >= NN) return;

    const float4* ap = reinterpret_cast<const float4*>(g_agg1 + (size_t)n * 16);
    float h[16];
    float4 t0 = ap[0], t1 = ap[1], t2 = ap[2], t3 = ap[3];
    h[0] = t0.x; h[1] = t0.y; h[2]  = t0.z; h[3]  = t0.w;
    h[4] = t1.x; h[5] = t1.y; h[6]  = t1.z; h[7]  = t1.w;
    h[8] = t2.x; h[9] = t2.y; h[10] = t2.z; h[11] = t2.w;
    h[12] = t3.x; h[13] = t3.y; h[14] = t3.z; h[15] = t3.w;
    #pragma unroll
    for (int j = 0; j < 16; j++) h[j] = fmaxf(h[j] + b1s[j], 0.f);

    float o[8];
    #pragma unroll
    for (int c = 0; c < 7; c++) {
        float s = 0.f;
        #pragma unroll
        for (int j = 0; j < 16; j++) s = fmaf(h[j], w2s[j * 7 + c], s);
        o[c] = s;
    }
    o[7] = 0.f;

    float4* op = reinterpret_cast<float4*>(g_h2 + (size_t)n * 8);
    op[0] = make_float4(o[0], o[1], o[2], o[3]);
    op[1] = make_float4(o[4], o[5], o[6], o[7]);
}

// ---------------------------------------------------------------------------
// Scatter2: agg2[dst] += h2[src].  2 lanes per edge, 16 edges per warp.
// ---------------------------------------------------------------------------
__global__ __launch_bounds__(256) void k_scatter2(const void* __restrict__ ei) {
    int warpGlobal = (blockIdx.x * 256 + threadIdx.x) >> 5;
    int lane = threadIdx.x & 31;
    int e_base = warpGlobal * 16;                 // EE = 25000*8*16 exactly
    int s = 0, d = 0;
    if (lane < 16) {
        int e = e_base + lane;
        if (g_is64) {
            const long long* p = (const long long*)ei;
            s = (int)p[e];
            d = (int)p[EE + e];
        } else {
            const int* p = (const int*)ei;
            s = p[e];
            d = p[EE + e];
        }
    }
    int eloc = lane >> 1;
    int src = __shfl_sync(0xffffffffu, s, eloc);
    int dst = __shfl_sync(0xffffffffu, d, eloc);
    if ((unsigned)src >= NN || (unsigned)dst >= NN) return;
    int chunk = lane & 1;
    float4 v = reinterpret_cast<const float4*>(g_h2)[src * 2 + chunk];
    red_add_v4(g_agg2 + (size_t)dst * 8 + chunk * 4, v);
}

// ---------------------------------------------------------------------------
// Epilogue: out[n][c] = agg2[n][c] + b2[c]   (strips the padding)
// ---------------------------------------------------------------------------
__global__ void k_final(const float* __restrict__ b2, float* __restrict__ out) {
    int i = blockIdx.x * blockDim.x + threadIdx.x;
    if (i >= NN * N_CLS) return;
    int n = i / 7;
    int c = i - n * 7;
    out[i] = g_agg2[n * 8 + c] + b2[c];
}

// ---------------------------------------------------------------------------
extern "C" void kernel_launch(void* const* d_in, const int* in_sizes, int n_in,
                              void* d_out, int out_size) {
    // Map inputs by element count (all six are distinct) — immune to ordering.
    const float* x  = nullptr;
    const void*  ei = nullptr;
    const float* W1 = nullptr;
    const float* b1 = nullptr;
    const float* W2 = nullptr;
    const float* b2 = nullptr;
    for (int i = 0; i < n_in; i++) {
        switch (in_sizes[i]) {
            case NN * D_IN:        x  = (const float*)d_in[i]; break;  // 51,200,000
            case 2 * EE:           ei = d_in[i];                break;  // 6,400,000
            case D_IN * D_HID:     W1 = (const float*)d_in[i]; break;  // 8192
            case D_HID:            b1 = (const float*)d_in[i]; break;  // 16
            case D_HID * N_CLS:    W2 = (const float*)d_in[i]; break;  // 112
            case N_CLS:            b2 = (const float*)d_in[i]; break;  // 7
            default: break;
        }
    }
    float* out = (float*)d_out;

    k_init<<<(NN * 6 + 255) / 256, 256>>>((const int*)ei);
    k_gemm1<<<NN / 16, 256>>>(x, W1);
    k_scatter1<<<EE / 64, 256>>>(ei);
    k_gemm2<<<(NN + 255) / 256, 256>>>(b1, W2);
    k_scatter2<<<EE / 128, 256>>>(ei);
    k_final<<<(NN * N_CLS + 255) / 256, 256>>>(b2, out);
}

// round 10
// speedup vs baseline: 1.4647x; 1.0447x over previous
#include <cuda_runtime.h>
#include <cstdint>

#define NN 100000
#define EE 3200000
#define D_IN 512
#define D_HID 16
#define N_CLS 7

typedef unsigned long long ull;

// Scratch (device globals: allocation-free per harness rules)
__device__ __align__(16) float g_h1[NN * D_HID];     // x @ W1
__device__ __align__(16) float g_agg1[NN * D_HID];   // scatter-add of h1
__device__ __align__(16) float g_h2[NN * 8];         // relu(agg1+b1) @ W2, padded 7->8
__device__ __align__(16) float g_agg2[NN * 8];       // scatter-add of h2, padded
__device__ int g_is64;                               // edge-index dtype flag

__device__ __forceinline__ void red_add_v4(float* addr, float4 v) {
    asm volatile("{ .reg .u64 ga;\n\t"
                 "cvta.to.global.u64 ga, %0;\n\t"
                 "red.global.add.v4.f32 [ga], {%1,%2,%3,%4}; }"
                 :: "l"(addr), "f"(v.x), "f"(v.y), "f"(v.z), "f"(v.w)
                 : "memory");
}

// Packed f32x2 FMA: a += x * w elementwise on two packed floats.
__device__ __forceinline__ void fma2(ull& a, ull x, ull w) {
    asm("fma.rn.f32x2 %0, %1, %2, %0;" : "+l"(a) : "l"(x), "l"(w));
}
__device__ __forceinline__ ull splat2(float f) {
    ull r;
    asm("mov.b64 %0, {%1,%1};" : "=l"(r) : "f"(f));
    return r;
}

__device__ __forceinline__ uint32_t smem_u32(const void* p) {
    uint32_t a;
    asm("{ .reg .u64 t; cvta.to.shared.u64 t, %1; cvt.u32.u64 %0, t; }"
        : "=r"(a) : "l"(p));
    return a;
}
__device__ __forceinline__ void cpa16(uint32_t dst, const void* src) {
    asm volatile("cp.async.cg.shared.global [%0], [%1], 16;" :: "r"(dst), "l"(src));
}
__device__ __forceinline__ void cpa_commit() {
    asm volatile("cp.async.commit_group;");
}
template <int N>
__device__ __forceinline__ void cpa_wait() {
    asm volatile("cp.async.wait_group %0;" :: "n"(N));
}

// ---------------------------------------------------------------------------
// Init: zero accumulators (every launch: graph replay) + edge dtype detect.
// int64 node-ids (<2^31) have all-zero odd 32b words.
// ---------------------------------------------------------------------------
__global__ void k_init(const int* __restrict__ ei) {
    int i = blockIdx.x * blockDim.x + threadIdx.x;
    if (i == 0) {
        int s = 0;
        #pragma unroll
        for (int t = 1; t < 64; t += 2) s |= ei[t];
        g_is64 = (s == 0) ? 1 : 0;
    }
    float4 z = make_float4(0.f, 0.f, 0.f, 0.f);
    if (i < NN * 4) {                       // agg1: NN*16 floats = NN*4 float4
        reinterpret_cast<float4*>(g_agg1)[i] = z;
    }
    int j = i - NN * 4;
    if (j >= 0 && j < NN * 2) {             // agg2: NN*8 floats = NN*2 float4
        reinterpret_cast<float4*>(g_agg2)[j] = z;
    }
}

// ---------------------------------------------------------------------------
// GEMM1 (x-stationary): thread = node, 16 outputs in 8 packed ull regs.
// x tile double-buffered in smem via cp.async (staging latency hidden);
// W1 rows are BROADCAST LDS (all lanes same address -> ~free crossbar).
// Pitch 36 floats (144B): 16B-aligned for cp.async; LDS.128 x-reads are
// phase-conflict-free (bank = 4*lane + kk4 covers all 32 banks per phase).
// ---------------------------------------------------------------------------
#define G1_T   128            // threads = nodes per block
#define G1_KC  32             // K chunk
#define G1_NCH (D_IN / G1_KC) // 16 chunks
#define G1_XP  36             // x row pitch in floats (144B)
#define G1_BLOCKS ((NN + G1_T - 1) / G1_T)   // 782

__global__ __launch_bounds__(G1_T) void k_gemm1(const float* __restrict__ x,
                                                const float* __restrict__ W1) {
    __shared__ float xs[2][G1_T][G1_XP];    // 36864 B
    __shared__ float wsc[2][G1_KC][16];     //  4096 B

    int tid = threadIdx.x;
    int nbase = blockIdx.x * G1_T;
    int gn = nbase + tid;

    // Stage chunk kc into buffer b (x transposed-free: row = node, 16B pieces).
    auto stage = [&](int kc, int b) {
        #pragma unroll
        for (int r = 0; r < 8; r++) {
            int idx = r * G1_T + tid;       // 0..1023
            int mm  = idx >> 3;             // node 0..127
            int kk4 = (idx & 7) * 4;        // k offset 0,4,..,28
            int gm  = nbase + mm;
            if (gm < NN) {
                uint32_t dst = smem_u32(&xs[b][mm][kk4]);
                cpa16(dst, x + (size_t)gm * D_IN + kc * G1_KC + kk4);
            }
        }
        // W1 chunk: 512 floats, 4 per thread, 16B each.
        {
            uint32_t dst = smem_u32(&wsc[b][0][0]) + tid * 16;
            cpa16(dst, W1 + kc * (G1_KC * 16) + tid * 4);
        }
    };

    ull acc[8];
    #pragma unroll
    for (int j = 0; j < 8; j++) acc[j] = 0ull;

    stage(0, 0);
    cpa_commit();

    for (int kc = 0; kc < G1_NCH; kc++) {
        int b = kc & 1;
        if (kc < G1_NCH - 1) {
            stage(kc + 1, (kc + 1) & 1);
            cpa_commit();
            cpa_wait<1>();                  // buffer b complete (1 group in flight)
        } else {
            cpa_wait<0>();
        }
        __syncthreads();                    // all threads' copies visible

        const float4* xrow = reinterpret_cast<const float4*>(&xs[b][tid][0]);
        #pragma unroll
        for (int g = 0; g < 8; g++) {
            float4 xv = xrow[g];            // LDS.128, conflict-free phases
            #pragma unroll
            for (int s = 0; s < 4; s++) {
                float xf = (s == 0) ? xv.x : (s == 1) ? xv.y : (s == 2) ? xv.z : xv.w;
                ull x2 = splat2(xf);
                const ull* wrow = reinterpret_cast<const ull*>(&wsc[b][g * 4 + s][0]);
                #pragma unroll
                for (int j = 0; j < 8; j++)
                    fma2(acc[j], x2, wrow[j]);   // broadcast LDS.64
            }
        }
        __syncthreads();                    // compute done before buf reuse
    }

    if (gn < NN) {
        ulonglong2* op = reinterpret_cast<ulonglong2*>(g_h1 + (size_t)gn * 16);
        ulonglong2 v0, v1, v2, v3;
        v0.x = acc[0]; v0.y = acc[1];
        v1.x = acc[2]; v1.y = acc[3];
        v2.x = acc[4]; v2.y = acc[5];
        v3.x = acc[6]; v3.y = acc[7];
        op[0] = v0; op[1] = v1; op[2] = v2; op[3] = v3;
    }
}

// ---------------------------------------------------------------------------
// Scatter1: agg1[dst] += h1[src].  4 lanes per edge (one 16B chunk each) so
// gathers of a 64B row coalesce into the same 128B line. 8 edges per warp.
// ---------------------------------------------------------------------------
__global__ __launch_bounds__(256) void k_scatter1(const void* __restrict__ ei) {
    int warpGlobal = (blockIdx.x * 256 + threadIdx.x) >> 5;
    int lane = threadIdx.x & 31;
    int e_base = warpGlobal * 8;                  // EE = 50000*8*8 exactly
    int s = 0, d = 0;
    if (lane < 8) {
        int e = e_base + lane;
        if (g_is64) {
            const long long* p = (const long long*)ei;
            s = (int)p[e];
            d = (int)p[EE + e];
        } else {
            const int* p = (const int*)ei;
            s = p[e];
            d = p[EE + e];
        }
    }
    int eloc = lane >> 2;
    int src = __shfl_sync(0xffffffffu, s, eloc);
    int dst = __shfl_sync(0xffffffffu, d, eloc);
    if ((unsigned)src >= NN || (unsigned)dst >= NN) return;
    int chunk = lane & 3;
    float4 v = reinterpret_cast<const float4*>(g_h1)[src * 4 + chunk];
    red_add_v4(g_agg1 + (size_t)dst * 16 + chunk * 4, v);
}

// ---------------------------------------------------------------------------
// GEMM2: g_h2 = relu(agg1 + b1) @ W2  (row padded to 8 floats, last = 0)
// ---------------------------------------------------------------------------
__global__ __launch_bounds__(256) void k_gemm2(const float* __restrict__ b1,
                                               const float* __restrict__ W2) {
    __shared__ float w2s[16 * 7];
    __shared__ float b1s[16];
    if (threadIdx.x < 112) w2s[threadIdx.x] = W2[threadIdx.x];
    if (threadIdx.x < 16)  b1s[threadIdx.x] = b1[threadIdx.x];
    __syncthreads();

    int n = blockIdx.x * blockDim.x + threadIdx.x;
    if (n >= NN) return;

    const float4* ap = reinterpret_cast<const float4*>(g_agg1 + (size_t)n * 16);
    float h[16];
    float4 t0 = ap[0], t1 = ap[1], t2 = ap[2], t3 = ap[3];
    h[0] = t0.x; h[1] = t0.y; h[2]  = t0.z; h[3]  = t0.w;
    h[4] = t1.x; h[5] = t1.y; h[6]  = t1.z; h[7]  = t1.w;
    h[8] = t2.x; h[9] = t2.y; h[10] = t2.z; h[11] = t2.w;
    h[12] = t3.x; h[13] = t3.y; h[14] = t3.z; h[15] = t3.w;
    #pragma unroll
    for (int j = 0; j < 16; j++) h[j] = fmaxf(h[j] + b1s[j], 0.f);

    float o[8];
    #pragma unroll
    for (int c = 0; c < 7; c++) {
        float s = 0.f;
        #pragma unroll
        for (int j = 0; j < 16; j++) s = fmaf(h[j], w2s[j * 7 + c], s);
        o[c] = s;
    }
    o[7] = 0.f;

    float4* op = reinterpret_cast<float4*>(g_h2 + (size_t)n * 8);
    op[0] = make_float4(o[0], o[1], o[2], o[3]);
    op[1] = make_float4(o[4], o[5], o[6], o[7]);
}

// ---------------------------------------------------------------------------
// Scatter2: agg2[dst] += h2[src].  2 lanes per edge, 16 edges per warp.
// ---------------------------------------------------------------------------
__global__ __launch_bounds__(256) void k_scatter2(const void* __restrict__ ei) {
    int warpGlobal = (blockIdx.x * 256 + threadIdx.x) >> 5;
    int lane = threadIdx.x & 31;
    int e_base = warpGlobal * 16;                 // EE = 25000*8*16 exactly
    int s = 0, d = 0;
    if (lane < 16) {
        int e = e_base + lane;
        if (g_is64) {
            const long long* p = (const long long*)ei;
            s = (int)p[e];
            d = (int)p[EE + e];
        } else {
            const int* p = (const int*)ei;
            s = p[e];
            d = p[EE + e];
        }
    }
    int eloc = lane >> 1;
    int src = __shfl_sync(0xffffffffu, s, eloc);
    int dst = __shfl_sync(0xffffffffu, d, eloc);
    if ((unsigned)src >= NN || (unsigned)dst >= NN) return;
    int chunk = lane & 1;
    float4 v = reinterpret_cast<const float4*>(g_h2)[src * 2 + chunk];
    red_add_v4(g_agg2 + (size_t)dst * 8 + chunk * 4, v);
}

// ---------------------------------------------------------------------------
// Epilogue: out[n][c] = agg2[n][c] + b2[c]   (strips the padding)
// ---------------------------------------------------------------------------
__global__ void k_final(const float* __restrict__ b2, float* __restrict__ out) {
    int i = blockIdx.x * blockDim.x + threadIdx.x;
    if (i >= NN * N_CLS) return;
    int n = i / 7;
    int c = i - n * 7;
    out[i] = g_agg2[n * 8 + c] + b2[c];
}

// ---------------------------------------------------------------------------
extern "C" void kernel_launch(void* const* d_in, const int* in_sizes, int n_in,
                              void* d_out, int out_size) {
    // Map inputs by element count (all six are distinct) — immune to ordering.
    const float* x  = nullptr;
    const void*  ei = nullptr;
    const float* W1 = nullptr;
    const float* b1 = nullptr;
    const float* W2 = nullptr;
    const float* b2 = nullptr;
    for (int i = 0; i < n_in; i++) {
        switch (in_sizes[i]) {
            case NN * D_IN:        x  = (const float*)d_in[i]; break;  // 51,200,000
            case 2 * EE:           ei = d_in[i];                break;  // 6,400,000
            case D_IN * D_HID:     W1 = (const float*)d_in[i]; break;  // 8192
            case D_HID:            b1 = (const float*)d_in[i]; break;  // 16
            case D_HID * N_CLS:    W2 = (const float*)d_in[i]; break;  // 112
            case N_CLS:            b2 = (const float*)d_in[i]; break;  // 7
            default: break;
        }
    }
    float* out = (float*)d_out;

    k_init<<<(NN * 6 + 255) / 256, 256>>>((const int*)ei);
    k_gemm1<<<G1_BLOCKS, G1_T>>>(x, W1);
    k_scatter1<<<EE / 64, 256>>>(ei);
    k_gemm2<<<(NN + 255) / 256, 256>>>(b1, W2);
    k_scatter2<<<EE / 128, 256>>>(ei);
    k_final<<<(NN * N_CLS + 255) / 256, 256>>>(b2, out);
}